// round 15
// baseline (speedup 1.0000x reference)
#include <cuda_runtime.h>
#include <cstdint>

// Problem constants
#define B_ROWS   65536
#define C_COLS   300
#define A_DIM    32
#define XSTRIDE  600

#define THREADS  256
#define NWARPS   8
#define GROUP    32
#define NGROUPS  (B_ROWS / GROUP)        // 2048
#define GRID     NGROUPS                 // one group per CTA

#define IDXCAP   40

#define CPS      156                     // cardsp stride (half2 words): conflict-free
#define APS      36                      // apbuf stride (floats)

#define CP_WORDS    (GROUP * CPS)        // 4992
#define AP_WORDS    (GROUP * APS)        // 1152
#define PW_WORDS    96
#define SMEM_WORDS  (CP_WORDS + AP_WORDS + NWARPS * PW_WORDS)  // 6912
#define SMEM_BYTES  (SMEM_WORDS * 4)     // 27648 B -> 7 CTAs/SM

// fp16-packed W, written once by pack_w_kernel: [kp][a] = half2{W[2kp][a], W[2kp+1][a]}
__device__ uint32_t g_Wp[152 * 32];      // kp >= 150 zero-padded

__device__ __forceinline__ uint32_t pack_f16x2(float lo, float hi) {
    uint32_t r;                          // first src -> hi half, second -> lo half
    asm("cvt.rn.f16x2.f32 %0, %1, %2;" : "=r"(r) : "f"(hi), "f"(lo));
    return r;
}
__device__ __forceinline__ void mma_f16_k16(float& d0, float& d1, float& d2, float& d3,
                                            uint32_t a0, uint32_t a1, uint32_t a2, uint32_t a3,
                                            uint32_t b0, uint32_t b1) {
    asm("mma.sync.aligned.m16n8k16.row.col.f32.f16.f16.f32 "
        "{%0,%1,%2,%3},{%4,%5,%6,%7},{%8,%9},{%0,%1,%2,%3};"
        : "+f"(d0), "+f"(d1), "+f"(d2), "+f"(d3)
        : "r"(a0), "r"(a1), "r"(a2), "r"(a3), "r"(b0), "r"(b1));
}

__global__ void pack_w_kernel(const float* __restrict__ W) {
    int i = blockIdx.x * blockDim.x + threadIdx.x;
    if (i < 152 * 32) {
        int kp = i >> 5, a = i & 31;
        float lo = (2 * kp     < C_COLS) ? W[(2 * kp)     * A_DIM + a] : 0.0f;
        float hi = (2 * kp + 1 < C_COLS) ? W[(2 * kp + 1) * A_DIM + a] : 0.0f;
        g_Wp[i] = pack_f16x2(lo, hi);
    }
}

__global__ __launch_bounds__(THREADS, 7)
void draftbot_kernel(const float* __restrict__ X,
                     const float* __restrict__ W,
                     float* __restrict__ Out)
{
    extern __shared__ uint32_t smw[];
    uint32_t* cardsp = smw;                          // [32][156] half2 (row x k-pairs)
    float*    apbuf  = (float*)(smw + CP_WORDS);     // [32][36]
    const int tid  = threadIdx.x;
    const int lane = tid & 31;
    const int warp = tid >> 5;
    float* pw   = apbuf + AP_WORDS + warp * PW_WORDS;
    int*   widx = (int*)pw;                          // [40]
    float* scw  = pw + IDXCAP;                       // [40]
    int*   wcnt = (int*)(pw + 2 * IDXCAP);           // [1] compaction counter

    const int g = blockIdx.x;                        // this CTA's group

    // ---- stage cards of group g (f32 -> f16x2) ----
    {
        const float* gb = X + (size_t)g * GROUP * XSTRIDE + C_COLS;
        #pragma unroll 1
        for (int t = 0; t < 10; t++) {
            int idx = tid + THREADS * t;             // valid < 2400
            if (idx < GROUP * 75) {
                int row = idx / 75, ch = idx - row * 75;
                float4 v = *(const float4*)(gb + (size_t)row * XSTRIDE + 4 * ch);
                uint2 h;
                h.x = pack_f16x2(v.x, v.y);
                h.y = pack_f16x2(v.z, v.w);
                *(uint2*)(cardsp + row * CPS + 2 * ch) = h;
            }
        }
        if (tid < GROUP * 2) {                       // cardsp kp 150,151 = 0
            int r = tid >> 1, kp = 150 + (tid & 1);
            cardsp[r * CPS + kp] = 0u;
        }
    }
    __syncthreads();                                 // cards ready

    const unsigned FULL = 0xffffffffu;
    const int rt = warp & 1;                         // phase-1 row tile (16 rows)
    const int nt = warp >> 1;                        // phase-1 n tile (8 cols)
    const int gq = lane >> 2, tq = lane & 3;         // mma fragment coords
    const int qid = lane >> 3;                       // phase-2 octets
    const int sub = lane & 7;

    // ---------- phase 1: ap = cards @ W + 1  (fp16 m16n8k16, B from global L1) ----------
    {
        float d0 = 0.f, d1 = 0.f, d2 = 0.f, d3 = 0.f;
        const uint32_t* A0 = cardsp + (rt * 16 + gq) * CPS;
        const uint32_t* A1 = A0 + 8 * CPS;
        const uint32_t* Bp = g_Wp + nt * 8 + gq;     // L1-resident packed W
        #pragma unroll
        for (int kk = 0; kk < 19; kk++) {            // 19 * k16 = 304 (padded)
            const int kp0 = kk * 8;
            uint32_t a0 = A0[kp0 + tq];
            uint32_t a1 = A1[kp0 + tq];
            uint32_t a2 = A0[kp0 + tq + 4];
            uint32_t a3 = A1[kp0 + tq + 4];
            uint32_t b0 = __ldg(Bp + (kp0 + tq) * 32);
            uint32_t b1 = __ldg(Bp + (kp0 + tq + 4) * 32);
            mma_f16_k16(d0, d1, d2, d3, a0, a1, a2, a3, b0, b1);
        }
        float* ap0 = apbuf + (rt * 16 + gq) * APS + nt * 8 + 2 * tq;
        *(float2*)ap0             = make_float2(d0 + 1.f, d1 + 1.f);
        *(float2*)(ap0 + 8 * APS) = make_float2(d2 + 1.f, d3 + 1.f);
    }
    __syncthreads();                                 // ap ready

    // ---------- phase 2: 4 rows/warp, sparse scores + masked log-softmax ----------
    #pragma unroll 1
    for (int i = 0; i < 4; i++) {
        const int lrow = warp * 4 + i;
        const int grow = g * GROUP + lrow;

        // atomic compaction (order-free) of nonzero option columns
        if (lane == 0) *wcnt = 0;
        const float4* osrc = (const float4*)(X + (size_t)grow * XSTRIDE);
        float4 ovv[3];
        ovv[0] = osrc[lane];
        ovv[1] = (lane + 32 < 75) ? osrc[lane + 32] : make_float4(0,0,0,0);
        ovv[2] = (lane + 64 < 75) ? osrc[lane + 64] : make_float4(0,0,0,0);
        __syncwarp();                                // wcnt reset visible
        unsigned lm = 0;
        #pragma unroll
        for (int t = 0; t < 3; t++) {
            lm |= (ovv[t].x != 0.f ? 1u : 0u) << (4 * t + 0);
            lm |= (ovv[t].y != 0.f ? 1u : 0u) << (4 * t + 1);
            lm |= (ovv[t].z != 0.f ? 1u : 0u) << (4 * t + 2);
            lm |= (ovv[t].w != 0.f ? 1u : 0u) << (4 * t + 3);
        }
        int lc = __popc(lm);
        int base = 0;
        if (lc) base = atomicAdd(wcnt, lc);
        unsigned mm = lm;
        while (mm) {
            int b = __ffs(mm) - 1; mm &= mm - 1;
            if (base < IDXCAP) widx[base] = 4 * (lane + 32 * (b >> 2)) + (b & 3);
            base++;
        }
        __syncwarp();                                // widx + counter complete
        int cn = *wcnt;
        if (cn > IDXCAP) cn = IDXCAP;

        // scores: 8 lanes per column, 4 columns in flight (fp32 W from global, L1-hot)
        float4 av = *(const float4*)(apbuf + lrow * APS + sub * 4);
        const int nch = (cn + 3) >> 2;
        #pragma unroll 2
        for (int ch = 0; ch < nch; ch++) {
            int  j   = ch * 4 + qid;
            bool val = j < cn;
            int  c   = val ? widx[j] : 0;
            float4 wv = *(const float4*)(W + c * A_DIM + sub * 4);
            float p = av.x * wv.x + av.y * wv.y + av.z * wv.z + av.w * wv.w;
            p += __shfl_xor_sync(FULL, p, 1);
            p += __shfl_xor_sync(FULL, p, 2);
            p += __shfl_xor_sync(FULL, p, 4);
            if (val && sub == 0) scw[j] = p;
        }
        __syncwarp();

        // masked log-softmax (zeros always present in the row)
        int  j0 = lane, j1 = lane + 32;
        bool v0 = j0 < cn, v1 = j1 < cn;
        float s0 = v0 ? scw[j0] : 0.0f;
        float s1 = v1 ? scw[j1] : 0.0f;
        int   c0 = v0 ? widx[j0] : -1;
        int   c1 = v1 ? widx[j1] : -1;

        float m = fmaxf(fmaxf(s0, s1), 0.0f);
        #pragma unroll
        for (int o = 16; o > 0; o >>= 1) m = fmaxf(m, __shfl_xor_sync(FULL, m, o));

        float g0 = (s0 > 0.f) ? 1.f : ((s0 < 0.f) ? -1.f : 0.f);
        float g1 = (s1 > 0.f) ? 1.f : ((s1 < 0.f) ? -1.f : 0.f);
        float sum = g0 * __expf(s0 - m * g0) + g1 * __expf(s1 - m * g1);
        #pragma unroll
        for (int o = 16; o > 0; o >>= 1) sum += __shfl_xor_sync(FULL, sum, o);
        float lse = __logf(sum);

        float* orow = Out + (size_t)grow * C_COLS;
        #pragma unroll
        for (int t = 0; t < 3; t++) {
            int gi = lane + 32 * t;
            if (gi < 75) *(float4*)(orow + 4 * gi) = make_float4(0.f, 0.f, 0.f, 0.f);
        }
        __syncwarp();
        if (c0 >= 0) orow[c0] = g0 * ((s0 - m * g0) - lse);
        if (c1 >= 0) orow[c1] = g1 * ((s1 - m * g1) - lse);
        __syncwarp();
    }
}

extern "C" void kernel_launch(void* const* d_in, const int* in_sizes, int n_in,
                              void* d_out, int out_size)
{
    const float* X = (const float*)d_in[0];
    const float* W = (const float*)d_in[1];
    if (n_in >= 2 && in_sizes[0] < in_sizes[1]) {   // defensively order by size
        const float* t = X; X = W; W = t;
    }
    float* Out = (float*)d_out;

    cudaFuncSetAttribute(draftbot_kernel,
                         cudaFuncAttributeMaxDynamicSharedMemorySize, SMEM_BYTES);
    pack_w_kernel<<<19, 256>>>(W);
    draftbot_kernel<<<GRID, THREADS, SMEM_BYTES>>>(X, W, Out);
}

// round 16
// speedup vs baseline: 1.1227x; 1.1227x over previous
#include <cuda_runtime.h>
#include <cstdint>

// Problem constants
#define B_ROWS   65536
#define C_COLS   300
#define A_DIM    32
#define XSTRIDE  600

#define THREADS  256
#define NWARPS   8
#define GROUP    32
#define NGROUPS  (B_ROWS / GROUP)        // 2048
#define GRID     NGROUPS                 // one group per CTA

#define IDXCAP   40

#define CPS      156                     // cardsp stride (half2 words): conflict-free
#define APS      36                      // apbuf stride (floats)

#define CP_WORDS    (GROUP * CPS)        // 4992
#define AP_WORDS    (GROUP * APS)        // 1152
#define PW_WORDS    96
#define SMEM_WORDS  (CP_WORDS + AP_WORDS + NWARPS * PW_WORDS)  // 6912
#define SMEM_BYTES  (SMEM_WORDS * 4)     // 27648 B

// Lane-major fp16-packed W fragments, written once by pack_w_kernel.
// g_Wq[(kk*4 + nt)*32 + lane] = { b0, b1 } for that (kk, nt, lane):
//   lane = gq*4+tq, n = nt*8+gq, kpA = kk*8+tq, kpB = kpA+4
//   b0 = half2{W[2*kpA][n], W[2*kpA+1][n]}, b1 = half2{W[2*kpB][n], W[2*kpB+1][n]}
__device__ uint2 g_Wq[19 * 4 * 32];      // 2432 entries, k >= 300 zero-padded

__device__ __forceinline__ uint32_t pack_f16x2(float lo, float hi) {
    uint32_t r;                          // first src -> hi half, second -> lo half
    asm("cvt.rn.f16x2.f32 %0, %1, %2;" : "=r"(r) : "f"(hi), "f"(lo));
    return r;
}
__device__ __forceinline__ void mma_f16_k16(float& d0, float& d1, float& d2, float& d3,
                                            uint32_t a0, uint32_t a1, uint32_t a2, uint32_t a3,
                                            uint32_t b0, uint32_t b1) {
    asm("mma.sync.aligned.m16n8k16.row.col.f32.f16.f16.f32 "
        "{%0,%1,%2,%3},{%4,%5,%6,%7},{%8,%9},{%0,%1,%2,%3};"
        : "+f"(d0), "+f"(d1), "+f"(d2), "+f"(d3)
        : "r"(a0), "r"(a1), "r"(a2), "r"(a3), "r"(b0), "r"(b1));
}

__global__ void pack_w_kernel(const float* __restrict__ W) {
    int i = blockIdx.x * blockDim.x + threadIdx.x;
    if (i < 19 * 4 * 32) {
        int lane = i & 31, kkn = i >> 5;
        int kk = kkn >> 2, nt = kkn & 3;
        int gq = lane >> 2, tq = lane & 3;
        int a  = nt * 8 + gq;
        int kpA = kk * 8 + tq, kpB = kpA + 4;
        float a0 = (2 * kpA     < C_COLS) ? W[(2 * kpA)     * A_DIM + a] : 0.0f;
        float a1 = (2 * kpA + 1 < C_COLS) ? W[(2 * kpA + 1) * A_DIM + a] : 0.0f;
        float b0 = (2 * kpB     < C_COLS) ? W[(2 * kpB)     * A_DIM + a] : 0.0f;
        float b1 = (2 * kpB + 1 < C_COLS) ? W[(2 * kpB + 1) * A_DIM + a] : 0.0f;
        uint2 v;
        v.x = pack_f16x2(a0, a1);
        v.y = pack_f16x2(b0, b1);
        g_Wq[i] = v;
    }
}

__global__ __launch_bounds__(THREADS, 6)
void draftbot_kernel(const float* __restrict__ X,
                     const float* __restrict__ W,
                     float* __restrict__ Out)
{
    extern __shared__ uint32_t smw[];
    uint32_t* cardsp = smw;                          // [32][156] half2 (row x k-pairs)
    float*    apbuf  = (float*)(smw + CP_WORDS);     // [32][36]
    const int tid  = threadIdx.x;
    const int lane = tid & 31;
    const int warp = tid >> 5;
    float* pw   = apbuf + AP_WORDS + warp * PW_WORDS;
    int*   widx = (int*)pw;                          // [40]
    float* scw  = pw + IDXCAP;                       // [40]

    const int g = blockIdx.x;                        // this CTA's group

    // ---- stage cards of group g (f32 -> f16x2) ----
    {
        const float* gb = X + (size_t)g * GROUP * XSTRIDE + C_COLS;
        #pragma unroll 1
        for (int t = 0; t < 10; t++) {
            int idx = tid + THREADS * t;             // valid < 2400
            if (idx < GROUP * 75) {
                int row = idx / 75, ch = idx - row * 75;
                float4 v = *(const float4*)(gb + (size_t)row * XSTRIDE + 4 * ch);
                uint2 h;
                h.x = pack_f16x2(v.x, v.y);
                h.y = pack_f16x2(v.z, v.w);
                *(uint2*)(cardsp + row * CPS + 2 * ch) = h;
            }
        }
        if (tid < GROUP * 2) {                       // cardsp kp 150,151 = 0
            int r = tid >> 1, kp = 150 + (tid & 1);
            cardsp[r * CPS + kp] = 0u;
        }
    }
    __syncthreads();                                 // cards ready

    const unsigned FULL = 0xffffffffu;
    const int rt = warp & 1;                         // phase-1 row tile (16 rows)
    const int nt = warp >> 1;                        // phase-1 n tile (8 cols)
    const int gq = lane >> 2, tq = lane & 3;         // mma fragment coords
    const int qid = lane >> 3;                       // phase-2 octets
    const int sub = lane & 7;

    // ---------- phase 1: ap = cards @ W + 1  (fp16 m16n8k16, lane-major B) ----------
    {
        float d0 = 0.f, d1 = 0.f, d2 = 0.f, d3 = 0.f;
        const uint32_t* A0 = cardsp + (rt * 16 + gq) * CPS;
        const uint32_t* A1 = A0 + 8 * CPS;
        const uint2*    Bq = g_Wq + nt * 32 + lane;  // one LDG.64 per iter, 2 lines/warp
        #pragma unroll
        for (int kk = 0; kk < 19; kk++) {            // 19 * k16 = 304 (padded)
            const int kp0 = kk * 8;
            uint32_t a0 = A0[kp0 + tq];
            uint32_t a1 = A1[kp0 + tq];
            uint32_t a2 = A0[kp0 + tq + 4];
            uint32_t a3 = A1[kp0 + tq + 4];
            uint2 bw = __ldg(Bq + kk * 128);
            mma_f16_k16(d0, d1, d2, d3, a0, a1, a2, a3, bw.x, bw.y);
        }
        float* ap0 = apbuf + (rt * 16 + gq) * APS + nt * 8 + 2 * tq;
        *(float2*)ap0             = make_float2(d0 + 1.f, d1 + 1.f);
        *(float2*)(ap0 + 8 * APS) = make_float2(d2 + 1.f, d3 + 1.f);
    }
    __syncthreads();                                 // ap ready

    // ---------- phase 2: 4 rows/warp, sparse scores + masked log-softmax ----------
    #pragma unroll 1
    for (int i = 0; i < 4; i++) {
        const int lrow = warp * 4 + i;
        const int grow = g * GROUP + lrow;

        // scan-based compaction (order-free) of nonzero option columns
        const float4* osrc = (const float4*)(X + (size_t)grow * XSTRIDE);
        float4 ovv[3];
        ovv[0] = osrc[lane];
        ovv[1] = (lane + 32 < 75) ? osrc[lane + 32] : make_float4(0,0,0,0);
        ovv[2] = (lane + 64 < 75) ? osrc[lane + 64] : make_float4(0,0,0,0);
        unsigned lm = 0;
        #pragma unroll
        for (int t = 0; t < 3; t++) {
            lm |= (ovv[t].x != 0.f ? 1u : 0u) << (4 * t + 0);
            lm |= (ovv[t].y != 0.f ? 1u : 0u) << (4 * t + 1);
            lm |= (ovv[t].z != 0.f ? 1u : 0u) << (4 * t + 2);
            lm |= (ovv[t].w != 0.f ? 1u : 0u) << (4 * t + 3);
        }
        int lc = __popc(lm);
        int incl = lc;
        #pragma unroll
        for (int o = 1; o < 32; o <<= 1) {
            int n = __shfl_up_sync(FULL, incl, o);
            if (lane >= o) incl += n;
        }
        int cn = __shfl_sync(FULL, incl, 31);
        int pos = incl - lc;
        unsigned mm = lm;
        while (mm) {
            int b = __ffs(mm) - 1; mm &= mm - 1;
            if (pos < IDXCAP) widx[pos] = 4 * (lane + 32 * (b >> 2)) + (b & 3);
            pos++;
        }
        if (cn > IDXCAP) cn = IDXCAP;
        __syncwarp();

        // scores: 8 lanes per column, 4 columns in flight (fp32 W from global, L1-hot)
        float4 av = *(const float4*)(apbuf + lrow * APS + sub * 4);
        const int nch = (cn + 3) >> 2;
        #pragma unroll 2
        for (int ch = 0; ch < nch; ch++) {
            int  j   = ch * 4 + qid;
            bool val = j < cn;
            int  c   = val ? widx[j] : 0;
            float4 wv = *(const float4*)(W + c * A_DIM + sub * 4);
            float p = av.x * wv.x + av.y * wv.y + av.z * wv.z + av.w * wv.w;
            p += __shfl_xor_sync(FULL, p, 1);
            p += __shfl_xor_sync(FULL, p, 2);
            p += __shfl_xor_sync(FULL, p, 4);
            if (val && sub == 0) scw[j] = p;
        }
        __syncwarp();

        // masked log-softmax (zeros always present in the row)
        int  j0 = lane, j1 = lane + 32;
        bool v0 = j0 < cn, v1 = j1 < cn;
        float s0 = v0 ? scw[j0] : 0.0f;
        float s1 = v1 ? scw[j1] : 0.0f;
        int   c0 = v0 ? widx[j0] : -1;
        int   c1 = v1 ? widx[j1] : -1;

        float m = fmaxf(fmaxf(s0, s1), 0.0f);
        #pragma unroll
        for (int o = 16; o > 0; o >>= 1) m = fmaxf(m, __shfl_xor_sync(FULL, m, o));

        float g0 = (s0 > 0.f) ? 1.f : ((s0 < 0.f) ? -1.f : 0.f);
        float g1 = (s1 > 0.f) ? 1.f : ((s1 < 0.f) ? -1.f : 0.f);
        float sum = g0 * __expf(s0 - m * g0) + g1 * __expf(s1 - m * g1);
        #pragma unroll
        for (int o = 16; o > 0; o >>= 1) sum += __shfl_xor_sync(FULL, sum, o);
        float lse = __logf(sum);

        float* orow = Out + (size_t)grow * C_COLS;
        #pragma unroll
        for (int t = 0; t < 3; t++) {
            int gi = lane + 32 * t;
            if (gi < 75) *(float4*)(orow + 4 * gi) = make_float4(0.f, 0.f, 0.f, 0.f);
        }
        __syncwarp();
        if (c0 >= 0) orow[c0] = g0 * ((s0 - m * g0) - lse);
        if (c1 >= 0) orow[c1] = g1 * ((s1 - m * g1) - lse);
        __syncwarp();
    }
}

extern "C" void kernel_launch(void* const* d_in, const int* in_sizes, int n_in,
                              void* d_out, int out_size)
{
    const float* X = (const float*)d_in[0];
    const float* W = (const float*)d_in[1];
    if (n_in >= 2 && in_sizes[0] < in_sizes[1]) {   // defensively order by size
        const float* t = X; X = W; W = t;
    }
    float* Out = (float*)d_out;

    cudaFuncSetAttribute(draftbot_kernel,
                         cudaFuncAttributeMaxDynamicSharedMemorySize, SMEM_BYTES);
    pack_w_kernel<<<10, 256>>>(W);
    draftbot_kernel<<<GRID, THREADS, SMEM_BYTES>>>(X, W, Out);
}

// round 17
// speedup vs baseline: 1.2724x; 1.1333x over previous
#include <cuda_runtime.h>
#include <cstdint>

// Problem constants
#define B_ROWS   65536
#define C_COLS   300
#define A_DIM    32
#define XSTRIDE  600

#define THREADS  256
#define NWARPS   8
#define GROUP    32
#define NGROUPS  (B_ROWS / GROUP)        // 2048
#define GRID     NGROUPS                 // one group per CTA

#define IDXCAP   40

#define CPS      156                     // cardsp stride (half2 words): conflict-free
#define APS      36                      // apbuf stride (floats)

#define CP_WORDS    (GROUP * CPS)        // 4992
#define AP_WORDS    (GROUP * APS)        // 1152
#define PW_WORDS    96
#define SMEM_WORDS  (CP_WORDS + AP_WORDS + NWARPS * PW_WORDS)  // 6912
#define SMEM_BYTES  (SMEM_WORDS * 4)     // 27648 B

// Lane-major fp16-packed W fragments, written once by pack_w_kernel.
// g_Wq[(kk*4 + nt)*32 + lane] = { b0, b1 } for that (kk, nt, lane)
__device__ uint2 g_Wq[19 * 4 * 32];      // 2432 entries, k >= 300 zero-padded

__device__ __forceinline__ uint32_t pack_f16x2(float lo, float hi) {
    uint32_t r;                          // first src -> hi half, second -> lo half
    asm("cvt.rn.f16x2.f32 %0, %1, %2;" : "=r"(r) : "f"(hi), "f"(lo));
    return r;
}
__device__ __forceinline__ void mma_f16_k16(float& d0, float& d1, float& d2, float& d3,
                                            uint32_t a0, uint32_t a1, uint32_t a2, uint32_t a3,
                                            uint32_t b0, uint32_t b1) {
    asm("mma.sync.aligned.m16n8k16.row.col.f32.f16.f16.f32 "
        "{%0,%1,%2,%3},{%4,%5,%6,%7},{%8,%9},{%0,%1,%2,%3};"
        : "+f"(d0), "+f"(d1), "+f"(d2), "+f"(d3)
        : "r"(a0), "r"(a1), "r"(a2), "r"(a3), "r"(b0), "r"(b1));
}
__device__ __forceinline__ void ldsm_x4(uint32_t& r0, uint32_t& r1,
                                        uint32_t& r2, uint32_t& r3, uint32_t saddr) {
    asm volatile("ldmatrix.sync.aligned.m8n8.x4.shared.b16 {%0,%1,%2,%3}, [%4];"
                 : "=r"(r0), "=r"(r1), "=r"(r2), "=r"(r3) : "r"(saddr));
}

__global__ void pack_w_kernel(const float* __restrict__ W) {
    int i = blockIdx.x * blockDim.x + threadIdx.x;
    if (i < 19 * 4 * 32) {
        int lane = i & 31, kkn = i >> 5;
        int kk = kkn >> 2, nt = kkn & 3;
        int gq = lane >> 2, tq = lane & 3;
        int a  = nt * 8 + gq;
        int kpA = kk * 8 + tq, kpB = kpA + 4;
        float a0 = (2 * kpA     < C_COLS) ? W[(2 * kpA)     * A_DIM + a] : 0.0f;
        float a1 = (2 * kpA + 1 < C_COLS) ? W[(2 * kpA + 1) * A_DIM + a] : 0.0f;
        float b0 = (2 * kpB     < C_COLS) ? W[(2 * kpB)     * A_DIM + a] : 0.0f;
        float b1 = (2 * kpB + 1 < C_COLS) ? W[(2 * kpB + 1) * A_DIM + a] : 0.0f;
        uint2 v;
        v.x = pack_f16x2(a0, a1);
        v.y = pack_f16x2(b0, b1);
        g_Wq[i] = v;
    }
}

__global__ __launch_bounds__(THREADS, 6)
void draftbot_kernel(const float* __restrict__ X,
                     const float* __restrict__ W,
                     float* __restrict__ Out)
{
    extern __shared__ uint32_t smw[];
    uint32_t* cardsp = smw;                          // [32][156] half2 (row x k-pairs)
    float*    apbuf  = (float*)(smw + CP_WORDS);     // [32][36]
    const int tid  = threadIdx.x;
    const int lane = tid & 31;
    const int warp = tid >> 5;
    float* pw   = apbuf + AP_WORDS + warp * PW_WORDS;
    int*   widx = (int*)pw;                          // [40]
    float* scw  = pw + IDXCAP;                       // [40]

    const int g = blockIdx.x;                        // this CTA's group

    // ---- stage cards of group g (f32 -> f16x2): warp w owns rows 4w..4w+3 ----
    {
        const float* gb = X + (size_t)g * GROUP * XSTRIDE + C_COLS;
        #pragma unroll
        for (int rr = 0; rr < 4; rr++) {
            const int row = warp * 4 + rr;
            const float* src = gb + (size_t)row * XSTRIDE;
            uint32_t* dst = cardsp + row * CPS;
            #pragma unroll
            for (int t = 0; t < 3; t++) {
                int ch = lane + 32 * t;
                if (ch < 75) {
                    float4 v = *(const float4*)(src + 4 * ch);
                    uint2 h;
                    h.x = pack_f16x2(v.x, v.y);
                    h.y = pack_f16x2(v.z, v.w);
                    *(uint2*)(dst + 2 * ch) = h;
                }
            }
            if (lane < 2) dst[150 + lane] = 0u;      // zero-pad kp 150,151
        }
    }
    __syncthreads();                                 // cards ready

    const unsigned FULL = 0xffffffffu;
    const int rt = warp & 1;                         // phase-1 row tile (16 rows)
    const int nt = warp >> 1;                        // phase-1 n tile (8 cols)
    const int gq = lane >> 2, tq = lane & 3;         // mma fragment coords
    const int qid = lane >> 3;                       // phase-2 octets
    const int sub = lane & 7;

    // ---------- phase 1: ap = cards @ W + 1  (fp16 m16n8k16, ldmatrix A) ----------
    {
        float d0 = 0.f, d1 = 0.f, d2 = 0.f, d3 = 0.f;
        // ldmatrix lane address: matrix mi = lane>>3 -> (row offset, word offset)
        const int mi   = lane >> 3;
        const int arow = rt * 16 + (lane & 7) + (mi & 1) * 8;
        const int awrd = (mi >> 1) * 4;
        uint32_t abase = (uint32_t)__cvta_generic_to_shared(cardsp)
                       + (uint32_t)(arow * CPS + awrd) * 4;
        const uint2* Bq = g_Wq + nt * 32 + lane;     // one LDG.64 per iter
        #pragma unroll
        for (int kk = 0; kk < 19; kk++) {            // 19 * k16 = 304 (padded)
            uint32_t a0, a1, a2, a3;
            ldsm_x4(a0, a1, a2, a3, abase + kk * 32);
            uint2 bw = __ldg(Bq + kk * 128);
            mma_f16_k16(d0, d1, d2, d3, a0, a1, a2, a3, bw.x, bw.y);
        }
        float* ap0 = apbuf + (rt * 16 + gq) * APS + nt * 8 + 2 * tq;
        *(float2*)ap0             = make_float2(d0 + 1.f, d1 + 1.f);
        *(float2*)(ap0 + 8 * APS) = make_float2(d2 + 1.f, d3 + 1.f);
    }
    __syncthreads();                                 // ap ready

    // ---------- phase 2: 4 rows/warp, sparse scores + masked log-softmax ----------
    #pragma unroll 1
    for (int i = 0; i < 4; i++) {
        const int lrow = warp * 4 + i;
        const int grow = g * GROUP + lrow;

        // scan-based compaction (order-free) of nonzero option columns
        const float4* osrc = (const float4*)(X + (size_t)grow * XSTRIDE);
        float4 ovv[3];
        ovv[0] = osrc[lane];
        ovv[1] = (lane + 32 < 75) ? osrc[lane + 32] : make_float4(0,0,0,0);
        ovv[2] = (lane + 64 < 75) ? osrc[lane + 64] : make_float4(0,0,0,0);
        unsigned lm = 0;
        #pragma unroll
        for (int t = 0; t < 3; t++) {
            lm |= (ovv[t].x != 0.f ? 1u : 0u) << (4 * t + 0);
            lm |= (ovv[t].y != 0.f ? 1u : 0u) << (4 * t + 1);
            lm |= (ovv[t].z != 0.f ? 1u : 0u) << (4 * t + 2);
            lm |= (ovv[t].w != 0.f ? 1u : 0u) << (4 * t + 3);
        }
        int lc = __popc(lm);
        int incl = lc;
        #pragma unroll
        for (int o = 1; o < 32; o <<= 1) {
            int n = __shfl_up_sync(FULL, incl, o);
            if (lane >= o) incl += n;
        }
        int cn = __shfl_sync(FULL, incl, 31);
        int pos = incl - lc;
        unsigned mm = lm;
        while (mm) {
            int b = __ffs(mm) - 1; mm &= mm - 1;
            if (pos < IDXCAP) widx[pos] = 4 * (lane + 32 * (b >> 2)) + (b & 3);
            pos++;
        }
        if (cn > IDXCAP) cn = IDXCAP;
        __syncwarp();

        // scores: 8 lanes per column, 4 columns in flight (fp32 W from global, L1-hot)
        float4 av = *(const float4*)(apbuf + lrow * APS + sub * 4);
        const int nch = (cn + 3) >> 2;
        #pragma unroll 2
        for (int ch = 0; ch < nch; ch++) {
            int  j   = ch * 4 + qid;
            bool val = j < cn;
            int  c   = val ? widx[j] : 0;
            float4 wv = *(const float4*)(W + c * A_DIM + sub * 4);
            float p = av.x * wv.x + av.y * wv.y + av.z * wv.z + av.w * wv.w;
            p += __shfl_xor_sync(FULL, p, 1);
            p += __shfl_xor_sync(FULL, p, 2);
            p += __shfl_xor_sync(FULL, p, 4);
            if (val && sub == 0) scw[j] = p;
        }
        __syncwarp();

        // masked log-softmax (zeros always present in the row)
        int  j0 = lane, j1 = lane + 32;
        bool v0 = j0 < cn, v1 = j1 < cn;
        float s0 = v0 ? scw[j0] : 0.0f;
        float s1 = v1 ? scw[j1] : 0.0f;
        int   c0 = v0 ? widx[j0] : -1;
        int   c1 = v1 ? widx[j1] : -1;

        float m = fmaxf(fmaxf(s0, s1), 0.0f);
        #pragma unroll
        for (int o = 16; o > 0; o >>= 1) m = fmaxf(m, __shfl_xor_sync(FULL, m, o));

        float g0 = (s0 > 0.f) ? 1.f : ((s0 < 0.f) ? -1.f : 0.f);
        float g1 = (s1 > 0.f) ? 1.f : ((s1 < 0.f) ? -1.f : 0.f);
        float sum = g0 * __expf(s0 - m * g0) + g1 * __expf(s1 - m * g1);
        #pragma unroll
        for (int o = 16; o > 0; o >>= 1) sum += __shfl_xor_sync(FULL, sum, o);
        float lse = __logf(sum);

        float* orow = Out + (size_t)grow * C_COLS;
        #pragma unroll
        for (int t = 0; t < 3; t++) {
            int gi = lane + 32 * t;
            if (gi < 75) *(float4*)(orow + 4 * gi) = make_float4(0.f, 0.f, 0.f, 0.f);
        }
        __syncwarp();
        if (c0 >= 0) orow[c0] = g0 * ((s0 - m * g0) - lse);
        if (c1 >= 0) orow[c1] = g1 * ((s1 - m * g1) - lse);
        __syncwarp();
    }
}

extern "C" void kernel_launch(void* const* d_in, const int* in_sizes, int n_in,
                              void* d_out, int out_size)
{
    const float* X = (const float*)d_in[0];
    const float* W = (const float*)d_in[1];
    if (n_in >= 2 && in_sizes[0] < in_sizes[1]) {   // defensively order by size
        const float* t = X; X = W; W = t;
    }
    float* Out = (float*)d_out;

    cudaFuncSetAttribute(draftbot_kernel,
                         cudaFuncAttributeMaxDynamicSharedMemorySize, SMEM_BYTES);
    pack_w_kernel<<<10, 256>>>(W);
    draftbot_kernel<<<GRID, THREADS, SMEM_BYTES>>>(X, W, Out);
}